// round 10
// baseline (speedup 1.0000x reference)
#include <cuda_runtime.h>
#include <cuda_bf16.h>
#include <cstdint>

#define DI __device__ __forceinline__

namespace {
constexpr int S = 16384;
constexpr int C = 128;
constexpr int NU = 576;                // split-KV units (128-row tiles, <=2048-key spans)
constexpr float SCL = 0.08838834764831845f * 1.4426950408889634f;  // scale*log2e
}
// frame f has 8 tiles * ceil((f+1)/2) splits
__constant__ int cCUM[17] = {0,8,16,32,48,72,96,128,160,200,240,288,336,392,448,512,576};

__device__ __align__(128) __nv_bfloat16 g_xn[S * C];
__device__ __align__(128) uint8_t g_q8[S * C];
__device__ __align__(128) uint8_t g_k8[S * C];
__device__ __align__(128) uint8_t g_v8[S * C];
__device__ __align__(128) uint8_t g_vt8[C * S];          // V^T fp8, NATURAL key order
__device__ __align__(128) __nv_bfloat16 g_at[S * C];
__device__ __align__(128) __nv_bfloat16 g_wt[4][C * C];
__device__ __align__(128) float g_po[(size_t)NU * 16384]; // unnormalized partial O
__device__ __align__(128) float g_pl[NU * 128];           // partial l

DI uint32_t sptr(const void* p) { return (uint32_t)__cvta_generic_to_shared(p); }
DI void cp16(uint32_t s, const void* g) {
    asm volatile("cp.async.cg.shared.global [%0], [%1], 16;\n" :: "r"(s), "l"(g));
}
DI void cp_commit() { asm volatile("cp.async.commit_group;\n" ::: "memory"); }
template<int N> DI void cp_wait() { asm volatile("cp.async.wait_group %0;\n" :: "n"(N) : "memory"); }
DI float ex2(float x) { float y; asm("ex2.approx.f32 %0, %1;" : "=f"(y) : "f"(x)); return y; }
DI uint16_t f2e4m3x2(float lo, float hi) {       // byte0=lo, byte1=hi
    uint16_t r;
    asm("cvt.rn.satfinite.e4m3x2.f32 %0, %1, %2;" : "=h"(r) : "f"(hi), "f"(lo));
    return r;
}
DI void ldsm4(uint32_t* r, uint32_t a) {
    asm volatile("ldmatrix.sync.aligned.m8n8.x4.shared.b16 {%0,%1,%2,%3}, [%4];\n"
                 : "=r"(r[0]), "=r"(r[1]), "=r"(r[2]), "=r"(r[3]) : "r"(a));
}
DI void mma16816(float* d, const uint32_t* a, const uint32_t* b) {
    asm volatile("mma.sync.aligned.m16n8k16.row.col.f32.bf16.bf16.f32 "
                 "{%0,%1,%2,%3}, {%4,%5,%6,%7}, {%8,%9}, {%0,%1,%2,%3};\n"
                 : "+f"(d[0]), "+f"(d[1]), "+f"(d[2]), "+f"(d[3])
                 : "r"(a[0]), "r"(a[1]), "r"(a[2]), "r"(a[3]), "r"(b[0]), "r"(b[1]));
}
DI void mma_f8(float* d, const uint32_t* a, const uint32_t* b) {
    asm volatile("mma.sync.aligned.m16n8k32.row.col.f32.e4m3.e4m3.f32 "
                 "{%0,%1,%2,%3}, {%4,%5,%6,%7}, {%8,%9}, {%0,%1,%2,%3};\n"
                 : "+f"(d[0]), "+f"(d[1]), "+f"(d[2]), "+f"(d[3])
                 : "r"(a[0]), "r"(a[1]), "r"(a[2]), "r"(a[3]), "r"(b[0]), "r"(b[1]));
}
// bf16 tile layout (projection GEMMs): rows x 256B, chunk16B swizzled
DI uint32_t sw_off(int row, int ch) { return (uint32_t)(row * 256 + ((ch ^ (row & 7)) << 4)); }
// fp8 tile layout: rows x 128B, 8 chunks of 16B, swizzled
DI uint32_t off8(int row, int ch) { return (uint32_t)(row * 128 + ((ch ^ (row & 7)) << 4)); }
// key permutation (applied to K ONLY): kpat = sigma^-1 where sigma is the
// S-fragment -> PV-A-fragment position map; composition makes A-position p
// hold P(key p) in NATURAL order, so V stays unpermuted.
DI int kpat(int p) { int m = p >> 3, q = (p >> 1) & 3, e = p & 1;
                     return 16 * (m >> 1) + 4 * q + 2 * (m & 1) + e; }
template<int R, int NT>
DI void load_tile(uint32_t sbase, const __nv_bfloat16* g, int tid) {
#pragma unroll
    for (int i = 0; i < (R * 16) / NT; i++) {
        int idx = tid + i * NT;
        int row = idx >> 4, ch = idx & 15;
        cp16(sbase + sw_off(row, ch), g + row * 128 + ch * 8);
    }
}

// ---------------- 1) RMSNorm ----------------
__global__ void __launch_bounds__(256) k_norm(const float* __restrict__ x,
                                              const float* __restrict__ gamma) {
    int token = blockIdx.x * 8 + (threadIdx.x >> 5);
    int lane  = threadIdx.x & 31;
    float4 a = reinterpret_cast<const float4*>(x + token * 128)[lane];
    float ss = a.x * a.x + a.y * a.y + a.z * a.z + a.w * a.w;
#pragma unroll
    for (int m = 16; m; m >>= 1) ss += __shfl_xor_sync(0xffffffffu, ss, m);
    float sc = 11.313708498984761f / (sqrtf(ss) + 1e-8f);
    float4 gv = reinterpret_cast<const float4*>(gamma)[lane];
    __nv_bfloat162* o = reinterpret_cast<__nv_bfloat162*>(g_xn + token * 128) + lane * 2;
    o[0] = __floats2bfloat162_rn(a.x * sc * gv.x, a.y * sc * gv.y);
    o[1] = __floats2bfloat162_rn(a.z * sc * gv.z, a.w * sc * gv.w);
}

// ---------------- 2) weight transpose ----------------
__global__ void __launch_bounds__(256) k_wconv(const float* __restrict__ wq,
                                               const float* __restrict__ wk,
                                               const float* __restrict__ wv,
                                               const float* __restrict__ wo) {
    const float* src = blockIdx.y == 0 ? wq : blockIdx.y == 1 ? wk
                     : blockIdx.y == 2 ? wv : wo;
    int idx = blockIdx.x * 256 + threadIdx.x;
    int n = idx >> 7, k = idx & 127;
    g_wt[blockIdx.y][idx] = __float2bfloat16(src[k * 128 + n]);
}

// ---------------- 3) QKV GEMM (bf16 mma) -> fp8 outputs ----------------
__global__ void __launch_bounds__(256) k_qkv(const float* __restrict__ bq,
                                             const float* __restrict__ bk,
                                             const float* __restrict__ bv) {
    extern __shared__ __align__(1024) char smem[];
    uint32_t sA = sptr(smem), sB = sA + 128 * 256;
    int which = blockIdx.y;
    int tid = threadIdx.x, wid = tid >> 5, lane = tid & 31;
    load_tile<128, 256>(sA, g_xn + blockIdx.x * 128 * 128, tid);
    load_tile<128, 256>(sB, g_wt[which], tid);
    cp_commit(); cp_wait<0>(); __syncthreads();
    int agrp = lane >> 3, lr = lane & 7;
    int mrow = wid * 16 + lr + ((agrp & 1) << 3);
    float acc[16][4];
#pragma unroll
    for (int i = 0; i < 16; i++) { acc[i][0] = acc[i][1] = acc[i][2] = acc[i][3] = 0.f; }
#pragma unroll
    for (int kk2 = 0; kk2 < 4; kk2++) {
        uint32_t a0[4], a1[4];
        ldsm4(a0, sA + sw_off(mrow, 4 * kk2 +     (agrp >> 1)));
        ldsm4(a1, sA + sw_off(mrow, 4 * kk2 + 2 + (agrp >> 1)));
#pragma unroll
        for (int nt = 0; nt < 16; nt++) {
            uint32_t b[4];
            ldsm4(b, sB + sw_off(nt * 8 + lr, 4 * kk2 + agrp));
            mma16816(acc[nt], a0, b);
            mma16816(acc[nt], a1, b + 2);
        }
    }
    const float* bias = which == 0 ? bq : which == 1 ? bk : bv;
    uint8_t* out = which == 0 ? g_q8 : which == 1 ? g_k8 : g_v8;
    int r0 = blockIdx.x * 128 + wid * 16 + (lane >> 2);
    int cb = (lane & 3) * 2;
#pragma unroll
    for (int nt = 0; nt < 16; nt++) {
        int col = nt * 8 + cb;
        float b0 = bias[col], b1 = bias[col + 1];
        *reinterpret_cast<uint16_t*>(out + (size_t)r0 * 128 + col) =
            f2e4m3x2(acc[nt][0] + b0, acc[nt][1] + b1);
        *reinterpret_cast<uint16_t*>(out + (size_t)(r0 + 8) * 128 + col) =
            f2e4m3x2(acc[nt][2] + b0, acc[nt][3] + b1);
    }
}

// ---------------- 3b) V transpose (PLAIN — natural key order) ----------------
__global__ void __launch_bounds__(256) k_vt() {
    __shared__ uint8_t t[128][144];
    int kb = blockIdx.x, tid = threadIdx.x;
#pragma unroll
    for (int i = 0; i < 4; i++) {
        int idx = tid + i * 256;                 // 128 rows x 8 chunks16
        int row = idx >> 3, ch = idx & 7;
        *reinterpret_cast<uint4*>(&t[row][ch * 16]) =
            *reinterpret_cast<const uint4*>(g_v8 + (size_t)(kb * 128 + row) * 128 + ch * 16);
    }
    __syncthreads();
#pragma unroll
    for (int i = 0; i < 4; i++) {
        int idx = tid + i * 256;                 // 128 ch x 8 pos-groups
        int ch = idx >> 3, pg = idx & 7;
        uint8_t tmp[16];
#pragma unroll
        for (int j = 0; j < 16; j++) tmp[j] = t[pg * 16 + j][ch];
        *reinterpret_cast<uint4*>(g_vt8 + (size_t)ch * 16384 + kb * 128 + pg * 16) =
            *reinterpret_cast<uint4*>(tmp);
    }
}

// ---------------- 4) FP8 split-KV flash attention (fixed-max) ----------------
// 128-row Q-tile, 128-key chunks, ring-3 K/V, one sync per chunk.
__global__ void __launch_bounds__(256, 1) k_attn() {
    extern __shared__ __align__(1024) uint8_t sm[];
    uint32_t sb = sptr(sm);
    const uint32_t SQ = sb, SK = sb + 16384, SV = sb + 65536;
    int tid = threadIdx.x, wid = tid >> 5, lane = tid & 31;
    int q_ = lane & 3, lr = lane & 7, g = lane >> 3;
    int wr0 = wid * 16;

    int u = NU - 1 - (int)blockIdx.x;
    int f = 0;
#pragma unroll
    for (int i = 0; i < 16; i++) if (u >= cCUM[i + 1]) f = i + 1;
    int r = u - cCUM[f];
    int ns = (f >> 1) + 1;
    int tif = r / ns, sp = r - tif * ns;
    int q0 = (f * 8 + tif) * 128;
    int kc0 = sp * 16;
    int nc = min(16, (f + 1) * 8 - kc0);       // always 8 or 16

    // Q load (4 iters of 256 thr over 128 rows x 8 chunks)
#pragma unroll
    for (int i = 0; i < 4; i++) {
        int idx = tid + i * 256, row = idx >> 3, ch = idx & 7;
        cp16(SQ + off8(row, ch), g_q8 + (size_t)(q0 + row) * 128 + ch * 16);
    }
    // K chunk loader: rows permuted per-32 by kpat. V^T loader: natural order.
    auto loadK = [&](int slot, int c) {
#pragma unroll
        for (int i = 0; i < 4; i++) {
            int idx = tid + i * 256, row = idx >> 3, ch = idx & 7;
            int srow = c * 128 + ((row >> 5) << 5) + kpat(row & 31);
            cp16(SK + slot * 16384 + off8(row, ch), g_k8 + (size_t)srow * 128 + ch * 16);
        }
    };
    auto loadV = [&](int slot, int c) {
#pragma unroll
        for (int i = 0; i < 4; i++) {
            int idx = tid + i * 256, row = idx >> 3, ch = idx & 7;
            cp16(SV + slot * 16384 + off8(row, ch),
                 g_vt8 + (size_t)row * 16384 + c * 128 + ch * 16);
        }
    };
    loadK(0, kc0); loadV(0, kc0); cp_commit();
    loadK(1, kc0 + 1); loadV(1, kc0 + 1); cp_commit();

    float o[16][4];
#pragma unroll
    for (int j = 0; j < 16; j++) { o[j][0] = o[j][1] = o[j][2] = o[j][3] = 0.f; }
    float l0 = 0.f, l1 = 0.f;
    uint32_t qa[4][4];

    for (int i = 0; i < nc; i++) {
        cp_wait<1>();
        __syncthreads();
        if (i + 2 < nc) { int st = (i + 2) % 3; loadK(st, kc0 + i + 2); loadV(st, kc0 + i + 2); }
        cp_commit();
        if (i == 0) {
#pragma unroll
            for (int t = 0; t < 4; t++)
                ldsm4(qa[t], SQ + off8(wr0 + lr + (g & 1) * 8, 2 * t + (g >> 1)));
        }
        uint32_t kb = SK + (i % 3) * 16384, vb = SV + (i % 3) * 16384;

        // S = Q @ K^T (fp8), keys in kpat order
        float s[16][4];
#pragma unroll
        for (int m = 0; m < 16; m++) { s[m][0] = s[m][1] = s[m][2] = s[m][3] = 0.f; }
#pragma unroll
        for (int t = 0; t < 4; t++) {
#pragma unroll
            for (int nb = 0; nb < 8; nb++) {
                uint32_t bb[4];
                ldsm4(bb, kb + off8(nb * 16 + lr + (g >> 1) * 8, 2 * t + (g & 1)));
                mma_f8(s[2 * nb],     qa[t], bb);
                mma_f8(s[2 * nb + 1], qa[t], bb + 2);
            }
        }
        // fused fixed-max softmax + PV (A-fragment = natural key order)
#pragma unroll
        for (int t = 0; t < 4; t++) {
            float p[4][4];
#pragma unroll
            for (int j = 0; j < 4; j++) {
                p[j][0] = ex2(s[4 * t + j][0] * SCL);
                p[j][1] = ex2(s[4 * t + j][1] * SCL);
                p[j][2] = ex2(s[4 * t + j][2] * SCL);
                p[j][3] = ex2(s[4 * t + j][3] * SCL);
                l0 += p[j][0] + p[j][1];
                l1 += p[j][2] + p[j][3];
            }
            uint32_t pa[4];
            pa[0] = (uint32_t)f2e4m3x2(p[0][0], p[0][1]) | ((uint32_t)f2e4m3x2(p[1][0], p[1][1]) << 16);
            pa[1] = (uint32_t)f2e4m3x2(p[0][2], p[0][3]) | ((uint32_t)f2e4m3x2(p[1][2], p[1][3]) << 16);
            pa[2] = (uint32_t)f2e4m3x2(p[2][0], p[2][1]) | ((uint32_t)f2e4m3x2(p[3][0], p[3][1]) << 16);
            pa[3] = (uint32_t)f2e4m3x2(p[2][2], p[2][3]) | ((uint32_t)f2e4m3x2(p[3][2], p[3][3]) << 16);
#pragma unroll
            for (int cbk = 0; cbk < 8; cbk++) {
                uint32_t vv[4];
                ldsm4(vv, vb + off8(cbk * 16 + lr + (g >> 1) * 8, 2 * t + (g & 1)));
                mma_f8(o[2 * cbk],     pa, vv);
                mma_f8(o[2 * cbk + 1], pa, vv + 2);
            }
        }
    }

    // epilogue: quad-reduce l, store unnormalized partials
    l0 += __shfl_xor_sync(0xffffffffu, l0, 1);
    l0 += __shfl_xor_sync(0xffffffffu, l0, 2);
    l1 += __shfl_xor_sync(0xffffffffu, l1, 1);
    l1 += __shfl_xor_sync(0xffffffffu, l1, 2);
    int rr = wr0 + (lane >> 2);
    float* po = g_po + (size_t)u * 16384;
#pragma unroll
    for (int j = 0; j < 16; j++) {
        int col = j * 8 + 2 * q_;
        *reinterpret_cast<float2*>(po + rr * 128 + col)       = make_float2(o[j][0], o[j][1]);
        *reinterpret_cast<float2*>(po + (rr + 8) * 128 + col) = make_float2(o[j][2], o[j][3]);
    }
    if (q_ == 0) {
        g_pl[u * 128 + rr]     = l0;
        g_pl[u * 128 + rr + 8] = l1;
    }
}

// ---------------- 4b) combine (plain sums) ----------------
__global__ void __launch_bounds__(256) k_comb() {
    int t = blockIdx.x;
    int f = t >> 3;
    int ns = (f >> 1) + 1;
    int ub = cCUM[f] + (t & 7) * ns;
    int row = threadIdx.x >> 1;
    int c0 = (threadIdx.x & 1) * 64;
    float l = 0.f;
    for (int s = 0; s < ns; s++) l += g_pl[(ub + s) * 128 + row];
    float inv = 1.f / l;
    float4 acc[16];
#pragma unroll
    for (int j = 0; j < 16; j++) acc[j] = make_float4(0.f, 0.f, 0.f, 0.f);
    for (int s = 0; s < ns; s++) {
        const float4* p = reinterpret_cast<const float4*>(
            g_po + (size_t)(ub + s) * 16384 + (size_t)row * 128 + c0);
#pragma unroll
        for (int j = 0; j < 16; j++) {
            float4 v = p[j];
            acc[j].x += v.x; acc[j].y += v.y; acc[j].z += v.z; acc[j].w += v.w;
        }
    }
    __nv_bfloat162* dst = reinterpret_cast<__nv_bfloat162*>(g_at + (size_t)(t * 128 + row) * 128 + c0);
#pragma unroll
    for (int j = 0; j < 16; j++) {
        dst[2 * j]     = __floats2bfloat162_rn(acc[j].x * inv, acc[j].y * inv);
        dst[2 * j + 1] = __floats2bfloat162_rn(acc[j].z * inv, acc[j].w * inv);
    }
}

// ---------------- 5) out-proj + residual ----------------
__global__ void __launch_bounds__(256) k_oproj(const float* __restrict__ bo,
                                               const float* __restrict__ x,
                                               float* __restrict__ out) {
    extern __shared__ __align__(1024) char smem[];
    uint32_t sA = sptr(smem), sB = sA + 128 * 256;
    int tid = threadIdx.x, wid = tid >> 5, lane = tid & 31;
    load_tile<128, 256>(sA, g_at + blockIdx.x * 128 * 128, tid);
    load_tile<128, 256>(sB, g_wt[3], tid);
    cp_commit(); cp_wait<0>(); __syncthreads();
    int agrp = lane >> 3, lr = lane & 7;
    int mrow = wid * 16 + lr + ((agrp & 1) << 3);
    float acc[16][4];
#pragma unroll
    for (int i = 0; i < 16; i++) { acc[i][0] = acc[i][1] = acc[i][2] = acc[i][3] = 0.f; }
#pragma unroll
    for (int kk2 = 0; kk2 < 4; kk2++) {
        uint32_t a0[4], a1[4];
        ldsm4(a0, sA + sw_off(mrow, 4 * kk2 +     (agrp >> 1)));
        ldsm4(a1, sA + sw_off(mrow, 4 * kk2 + 2 + (agrp >> 1)));
#pragma unroll
        for (int nt = 0; nt < 16; nt++) {
            uint32_t b[4];
            ldsm4(b, sB + sw_off(nt * 8 + lr, 4 * kk2 + agrp));
            mma16816(acc[nt], a0, b);
            mma16816(acc[nt], a1, b + 2);
        }
    }
    int r0 = blockIdx.x * 128 + wid * 16 + (lane >> 2);
    int cb = (lane & 3) * 2;
#pragma unroll
    for (int nt = 0; nt < 16; nt++) {
        int col = nt * 8 + cb;
        float b0 = bo[col], b1 = bo[col + 1];
        *reinterpret_cast<float2*>(out + r0 * 128 + col) =
            make_float2(acc[nt][0] + b0 + x[r0 * 128 + col],
                        acc[nt][1] + b1 + x[r0 * 128 + col + 1]);
        *reinterpret_cast<float2*>(out + (r0 + 8) * 128 + col) =
            make_float2(acc[nt][2] + b0 + x[(r0 + 8) * 128 + col],
                        acc[nt][3] + b1 + x[(r0 + 8) * 128 + col + 1]);
    }
}

extern "C" void kernel_launch(void* const* d_in, const int* in_sizes, int n_in,
                              void* d_out, int out_size) {
    (void)in_sizes; (void)n_in; (void)out_size;
    const float* x     = (const float*)d_in[0];
    const float* gamma = (const float*)d_in[1];
    const float* wq = (const float*)d_in[2];
    const float* bq = (const float*)d_in[3];
    const float* wk = (const float*)d_in[4];
    const float* bk = (const float*)d_in[5];
    const float* wv = (const float*)d_in[6];
    const float* bv = (const float*)d_in[7];
    const float* wo = (const float*)d_in[8];
    const float* bo = (const float*)d_in[9];
    float* out = (float*)d_out;

    cudaFuncSetAttribute(k_qkv,   cudaFuncAttributeMaxDynamicSharedMemorySize, 65536);
    cudaFuncSetAttribute(k_oproj, cudaFuncAttributeMaxDynamicSharedMemorySize, 65536);
    cudaFuncSetAttribute(k_attn,  cudaFuncAttributeMaxDynamicSharedMemorySize, 114688);

    k_norm <<<S / 8, 256>>>(x, gamma);
    k_wconv<<<dim3(64, 4), 256>>>(wq, wk, wv, wo);
    k_qkv  <<<dim3(S / 128, 3), 256, 65536>>>(bq, bk, bv);
    k_vt   <<<128, 256>>>();
    k_attn <<<NU, 256, 114688>>>();
    k_comb <<<128, 256>>>();
    k_oproj<<<S / 128, 256, 65536>>>(bo, x, out);
}

// round 11
// speedup vs baseline: 1.2614x; 1.2614x over previous
#include <cuda_runtime.h>
#include <cuda_bf16.h>
#include <cstdint>

#define DI __device__ __forceinline__

namespace {
constexpr int S = 16384;      // tokens = 16*32*32
constexpr int C = 128;        // channels
constexpr int NUNITS = 1152;  // split-KV work units (64-row tiles, <=2048-key spans)
// (1/sqrt(128)) * log2(e): folded into Q so softmax uses exp2
constexpr float SCALE_LOG2E = 0.08838834764831845f * 1.4426950408889634f;
}

// cumulative split-KV units per frame: frame f has 16 tiles * ceil((f+1)/2) splits
__constant__ int cFCUM[17] = {0,16,32,64,96,144,192,256,320,400,480,576,672,784,896,1024,1152};

// ---------------- scratch (device globals; no allocs allowed) ----------------
__device__ __align__(128) __nv_bfloat16 g_xn[S * C];
__device__ __align__(128) __nv_bfloat16 g_q [S * C];
__device__ __align__(128) __nv_bfloat16 g_k [S * C];
__device__ __align__(128) __nv_bfloat16 g_v [S * C];
__device__ __align__(128) __nv_bfloat16 g_at[S * C];
__device__ __align__(128) __nv_bfloat16 g_wt[4][C * C];   // wt[n][k] = W[k][n]
__device__ __align__(128) float g_po[(size_t)NUNITS * 8192]; // unnormalized partial O
__device__ __align__(128) float g_pl[NUNITS * 64];           // partial l per row

// ---------------- small PTX helpers ----------------
DI uint32_t sptr(const void* p) { return (uint32_t)__cvta_generic_to_shared(p); }
DI void cp16(uint32_t s, const void* g) {
    asm volatile("cp.async.cg.shared.global [%0], [%1], 16;\n" :: "r"(s), "l"(g));
}
DI void cp_commit() { asm volatile("cp.async.commit_group;\n" ::: "memory"); }
template<int N> DI void cp_wait() { asm volatile("cp.async.wait_group %0;\n" :: "n"(N) : "memory"); }
DI float ex2(float x) { float y; asm("ex2.approx.f32 %0, %1;" : "=f"(y) : "f"(x)); return y; }

// tile layout: rows x 128 bf16 (256B/row, 16 chunks of 16B), XOR-swizzled
DI uint32_t sw_off(int row, int ch) { return (uint32_t)(row * 256 + ((ch ^ (row & 7)) << 4)); }

DI void ldsm4(uint32_t* r, uint32_t a) {
    asm volatile("ldmatrix.sync.aligned.m8n8.x4.shared.b16 {%0,%1,%2,%3}, [%4];\n"
                 : "=r"(r[0]), "=r"(r[1]), "=r"(r[2]), "=r"(r[3]) : "r"(a));
}
DI void ldsm4t(uint32_t* r, uint32_t a) {
    asm volatile("ldmatrix.sync.aligned.m8n8.x4.trans.shared.b16 {%0,%1,%2,%3}, [%4];\n"
                 : "=r"(r[0]), "=r"(r[1]), "=r"(r[2]), "=r"(r[3]) : "r"(a));
}
DI void mma16816(float* d, const uint32_t* a, const uint32_t* b) {
    asm volatile("mma.sync.aligned.m16n8k16.row.col.f32.bf16.bf16.f32 "
                 "{%0,%1,%2,%3}, {%4,%5,%6,%7}, {%8,%9}, {%0,%1,%2,%3};\n"
                 : "+f"(d[0]), "+f"(d[1]), "+f"(d[2]), "+f"(d[3])
                 : "r"(a[0]), "r"(a[1]), "r"(a[2]), "r"(a[3]), "r"(b[0]), "r"(b[1]));
}
DI uint32_t packbf(float lo, float hi) {
    __nv_bfloat162 t = __floats2bfloat162_rn(lo, hi);
    return *reinterpret_cast<uint32_t*>(&t);
}

// async copy of an [R x 128] bf16 row-major tile into swizzled smem
template<int R, int NT>
DI void load_tile(uint32_t sbase, const __nv_bfloat16* g, int tid) {
#pragma unroll
    for (int i = 0; i < (R * 16) / NT; i++) {
        int idx = tid + i * NT;
        int row = idx >> 4, ch = idx & 15;
        cp16(sbase + sw_off(row, ch), g + row * 128 + ch * 8);
    }
}

// ---------------- 1) RMSNorm -> bf16 xn ----------------
__global__ void __launch_bounds__(256) k_norm(const float* __restrict__ x,
                                              const float* __restrict__ gamma) {
    int token = blockIdx.x * 8 + (threadIdx.x >> 5);
    int lane  = threadIdx.x & 31;
    float4 a = reinterpret_cast<const float4*>(x + token * 128)[lane];
    float ss = a.x * a.x + a.y * a.y + a.z * a.z + a.w * a.w;
#pragma unroll
    for (int m = 16; m; m >>= 1) ss += __shfl_xor_sync(0xffffffffu, ss, m);
    float sc = 11.313708498984761f / (sqrtf(ss) + 1e-8f);
    float4 gv = reinterpret_cast<const float4*>(gamma)[lane];
    __nv_bfloat162* o = reinterpret_cast<__nv_bfloat162*>(g_xn + token * 128) + lane * 2;
    o[0] = __floats2bfloat162_rn(a.x * sc * gv.x, a.y * sc * gv.y);
    o[1] = __floats2bfloat162_rn(a.z * sc * gv.z, a.w * sc * gv.w);
}

// ---------------- 2) weight transpose + bf16 convert ----------------
__global__ void __launch_bounds__(256) k_wconv(const float* __restrict__ wq,
                                               const float* __restrict__ wk,
                                               const float* __restrict__ wv,
                                               const float* __restrict__ wo) {
    const float* src = blockIdx.y == 0 ? wq : blockIdx.y == 1 ? wk
                     : blockIdx.y == 2 ? wv : wo;
    int idx = blockIdx.x * 256 + threadIdx.x;
    int n = idx >> 7, k = idx & 127;
    g_wt[blockIdx.y][idx] = __float2bfloat16(src[k * 128 + n]);
}

// ---------------- 3) QKV projection GEMM (bf16 mma) ----------------
__global__ void __launch_bounds__(256) k_qkv(const float* __restrict__ bq,
                                             const float* __restrict__ bk,
                                             const float* __restrict__ bv) {
    extern __shared__ __align__(1024) char smem[];
    uint32_t sA = sptr(smem), sB = sA + 128 * 256;
    int which = blockIdx.y;
    int tid = threadIdx.x, wid = tid >> 5, lane = tid & 31;
    load_tile<128, 256>(sA, g_xn + blockIdx.x * 128 * 128, tid);
    load_tile<128, 256>(sB, g_wt[which], tid);
    cp_commit(); cp_wait<0>(); __syncthreads();
    int agrp = lane >> 3, lr = lane & 7;
    int mrow = wid * 16 + lr + ((agrp & 1) << 3);
    float acc[16][4];
#pragma unroll
    for (int i = 0; i < 16; i++) { acc[i][0] = acc[i][1] = acc[i][2] = acc[i][3] = 0.f; }
#pragma unroll
    for (int kk2 = 0; kk2 < 4; kk2++) {
        uint32_t a0[4], a1[4];
        ldsm4(a0, sA + sw_off(mrow, 4 * kk2 +     (agrp >> 1)));
        ldsm4(a1, sA + sw_off(mrow, 4 * kk2 + 2 + (agrp >> 1)));
#pragma unroll
        for (int nt = 0; nt < 16; nt++) {
            uint32_t b[4];
            ldsm4(b, sB + sw_off(nt * 8 + lr, 4 * kk2 + agrp));
            mma16816(acc[nt], a0, b);
            mma16816(acc[nt], a1, b + 2);
        }
    }
    const float* bias = which == 0 ? bq : which == 1 ? bk : bv;
    __nv_bfloat16* out = which == 0 ? g_q : which == 1 ? g_k : g_v;
    float mul = (which == 0) ? SCALE_LOG2E : 1.0f;   // fold softmax scale into Q
    int r0 = blockIdx.x * 128 + wid * 16 + (lane >> 2);
    int cb = (lane & 3) * 2;
#pragma unroll
    for (int nt = 0; nt < 16; nt++) {
        int col = nt * 8 + cb;
        float b0 = bias[col], b1 = bias[col + 1];
        *reinterpret_cast<__nv_bfloat162*>(out + r0 * 128 + col) =
            __floats2bfloat162_rn((acc[nt][0] + b0) * mul, (acc[nt][1] + b1) * mul);
        *reinterpret_cast<__nv_bfloat162*>(out + (r0 + 8) * 128 + col) =
            __floats2bfloat162_rn((acc[nt][2] + b0) * mul, (acc[nt][3] + b1) * mul);
    }
}

// ---------------- 4) split-KV flash attention (fixed-max, QK pipelined) ----------------
// Unit u = (64-row Q-tile, <=32-chunk key span). Ring-3 K/V, one sync per chunk.
// Fixed-max softmax (exact: |log2-scores| << 1) -> no max/rescale machinery.
// Iteration i issues QK(i+1) into the alternate s-set BEFORE softmax(i)+PV(i),
// so the tensor pipe drains QK(i+1) under the MUFU burst.
__global__ void __launch_bounds__(128, 2) k_attn() {
    extern __shared__ __align__(1024) char smem[];
    uint32_t sQ = sptr(smem);
    uint32_t sK[3], sV[3];
#pragma unroll
    for (int st = 0; st < 3; st++) {
        sK[st] = sQ + 16384 + st * 32768;
        sV[st] = sK[st] + 16384;
    }
    int tid = threadIdx.x, wid = tid >> 5, lane = tid & 31;

    int u = NUNITS - 1 - (int)blockIdx.x;   // heavy frames first
    int f = 0;
#pragma unroll
    for (int i = 0; i < 16; i++) if (u >= cFCUM[i + 1]) f = i + 1;
    int r   = u - cFCUM[f];
    int ns  = (f >> 1) + 1;
    int tif = r / ns;
    int s_  = r - tif * ns;
    int q0  = (f * 16 + tif) * 64;
    int kc0 = s_ * 32;
    int nc  = min(kc0 + 32, (f + 1) * 16) - kc0;   // 16 or 32 (always even)

    // prologue: G0 = Q + chunk0, G1 = chunk1
    load_tile<64, 128>(sQ, g_q + q0 * 128, tid);
    load_tile<64, 128>(sK[0], g_k + (size_t)kc0 * 8192, tid);
    load_tile<64, 128>(sV[0], g_v + (size_t)kc0 * 8192, tid);
    cp_commit();
    load_tile<64, 128>(sK[1], g_k + (size_t)(kc0 + 1) * 8192, tid);
    load_tile<64, 128>(sV[1], g_v + (size_t)(kc0 + 1) * 8192, tid);
    cp_commit();
    cp_wait<1>();              // G0 resident
    __syncthreads();

    int agrp = lane >> 3, lr = lane & 7;
    int mrow = wid * 16 + lr + ((agrp & 1) << 3);
    uint32_t qf[8][4];
#pragma unroll
    for (int kk = 0; kk < 8; kk++)
        ldsm4(qf[kk], sQ + sw_off(mrow, 2 * kk + (agrp >> 1)));

    float o[16][4];
#pragma unroll
    for (int j = 0; j < 16; j++) { o[j][0] = o[j][1] = o[j][2] = o[j][3] = 0.f; }
    float l0 = 0.f, l1 = 0.f;

    auto qk = [&](uint32_t kbuf, float (&s)[8][4]) {
#pragma unroll
        for (int nt = 0; nt < 8; nt++) { s[nt][0] = s[nt][1] = s[nt][2] = s[nt][3] = 0.f; }
#pragma unroll
        for (int kk2 = 0; kk2 < 4; kk2++) {
#pragma unroll
            for (int nt = 0; nt < 8; nt++) {
                uint32_t b[4];
                ldsm4(b, kbuf + sw_off(nt * 8 + lr, 4 * kk2 + agrp));
                mma16816(s[nt], qf[2 * kk2],     b);
                mma16816(s[nt], qf[2 * kk2 + 1], b + 2);
            }
        }
    };
    auto spv = [&](float (&s)[8][4], uint32_t vbuf) {
        uint32_t pf[4][4];
#pragma unroll
        for (int nt = 0; nt < 8; nt++) {
            float p0 = ex2(s[nt][0]);
            float p1 = ex2(s[nt][1]);
            float p2 = ex2(s[nt][2]);
            float p3 = ex2(s[nt][3]);
            l0 += p0 + p1;  l1 += p2 + p3;
            int kk = nt >> 1;
            if ((nt & 1) == 0) { pf[kk][0] = packbf(p0, p1); pf[kk][1] = packbf(p2, p3); }
            else               { pf[kk][2] = packbf(p0, p1); pf[kk][3] = packbf(p2, p3); }
        }
#pragma unroll
        for (int kk2 = 0; kk2 < 2; kk2++) {
#pragma unroll
            for (int j = 0; j < 16; j++) {
                uint32_t b[4];
                ldsm4t(b, vbuf + sw_off(kk2 * 32 + agrp * 8 + lr, j));
                mma16816(o[j], pf[2 * kk2],     b);
                mma16816(o[j], pf[2 * kk2 + 1], b + 2);
            }
        }
    };
    auto step = [&](float (&scur)[8][4], float (&snxt)[8][4], int i) {
        __syncthreads();                   // all warps done with bufs of iter i-1
        if (i + 2 < nc) {                  // refill slot (i+2)%3
            int st = (i + 2) % 3;
            load_tile<64, 128>(sK[st], g_k + (size_t)(kc0 + i + 2) * 8192, tid);
            load_tile<64, 128>(sV[st], g_v + (size_t)(kc0 + i + 2) * 8192, tid);
        }
        cp_commit();
        cp_wait<1>();                      // chunk i+1 resident
        if (i + 1 < nc) qk(sK[(i + 1) % 3], snxt);   // tensor work ahead of softmax
        spv(scur, sV[i % 3]);
    };

    float sE[8][4], sO[8][4];
    qk(sK[0], sE);                         // QK(0)
    for (int i = 0; i < nc; i += 2) {      // nc is even
        step(sE, sO, i);
        step(sO, sE, i + 1);
    }

    // ---- epilogue: quad-reduce l, store unnormalized partials ----
    l0 += __shfl_xor_sync(0xffffffffu, l0, 1);
    l0 += __shfl_xor_sync(0xffffffffu, l0, 2);
    l1 += __shfl_xor_sync(0xffffffffu, l1, 1);
    l1 += __shfl_xor_sync(0xffffffffu, l1, 2);
    int lr0 = wid * 16 + (lane >> 2);
    int cb  = (lane & 3) * 2;
    float* po = g_po + (size_t)u * 8192;
#pragma unroll
    for (int j = 0; j < 16; j++) {
        int col = j * 8 + cb;
        *reinterpret_cast<float2*>(po + lr0 * 128 + col)       = make_float2(o[j][0], o[j][1]);
        *reinterpret_cast<float2*>(po + (lr0 + 8) * 128 + col) = make_float2(o[j][2], o[j][3]);
    }
    if ((lane & 3) == 0) {
        g_pl[u * 64 + lr0]     = l0;
        g_pl[u * 64 + lr0 + 8] = l1;
    }
}

// ---------------- 4b) combine (plain sums) ----------------
__global__ void __launch_bounds__(256) k_comb() {
    int t  = blockIdx.x;
    int f  = t >> 4;
    int ns = (f >> 1) + 1;
    int ub = cFCUM[f] + (t & 15) * ns;
    int row = threadIdx.x >> 2;
    int c0  = (threadIdx.x & 3) * 32;
    float l = 0.f;
    for (int s = 0; s < ns; s++) l += g_pl[(ub + s) * 64 + row];
    float inv = 1.f / l;
    float4 acc[8];
#pragma unroll
    for (int j = 0; j < 8; j++) acc[j] = make_float4(0.f, 0.f, 0.f, 0.f);
    for (int s = 0; s < ns; s++) {
        const float4* p = reinterpret_cast<const float4*>(
            g_po + (size_t)(ub + s) * 8192 + row * 128 + c0);
#pragma unroll
        for (int j = 0; j < 8; j++) {
            float4 v = p[j];
            acc[j].x += v.x; acc[j].y += v.y; acc[j].z += v.z; acc[j].w += v.w;
        }
    }
    __nv_bfloat162* dst = reinterpret_cast<__nv_bfloat162*>(g_at + (t * 64 + row) * 128 + c0);
#pragma unroll
    for (int j = 0; j < 8; j++) {
        dst[2 * j]     = __floats2bfloat162_rn(acc[j].x * inv, acc[j].y * inv);
        dst[2 * j + 1] = __floats2bfloat162_rn(acc[j].z * inv, acc[j].w * inv);
    }
}

// ---------------- 5) output projection + bias + residual ----------------
__global__ void __launch_bounds__(256) k_oproj(const float* __restrict__ bo,
                                               const float* __restrict__ x,
                                               float* __restrict__ out) {
    extern __shared__ __align__(1024) char smem[];
    uint32_t sA = sptr(smem), sB = sA + 128 * 256;
    int tid = threadIdx.x, wid = tid >> 5, lane = tid & 31;
    load_tile<128, 256>(sA, g_at + blockIdx.x * 128 * 128, tid);
    load_tile<128, 256>(sB, g_wt[3], tid);
    cp_commit(); cp_wait<0>(); __syncthreads();
    int agrp = lane >> 3, lr = lane & 7;
    int mrow = wid * 16 + lr + ((agrp & 1) << 3);
    float acc[16][4];
#pragma unroll
    for (int i = 0; i < 16; i++) { acc[i][0] = acc[i][1] = acc[i][2] = acc[i][3] = 0.f; }
#pragma unroll
    for (int kk2 = 0; kk2 < 4; kk2++) {
        uint32_t a0[4], a1[4];
        ldsm4(a0, sA + sw_off(mrow, 4 * kk2 +     (agrp >> 1)));
        ldsm4(a1, sA + sw_off(mrow, 4 * kk2 + 2 + (agrp >> 1)));
#pragma unroll
        for (int nt = 0; nt < 16; nt++) {
            uint32_t b[4];
            ldsm4(b, sB + sw_off(nt * 8 + lr, 4 * kk2 + agrp));
            mma16816(acc[nt], a0, b);
            mma16816(acc[nt], a1, b + 2);
        }
    }
    int r0 = blockIdx.x * 128 + wid * 16 + (lane >> 2);
    int cb = (lane & 3) * 2;
#pragma unroll
    for (int nt = 0; nt < 16; nt++) {
        int col = nt * 8 + cb;
        float b0 = bo[col], b1 = bo[col + 1];
        *reinterpret_cast<float2*>(out + r0 * 128 + col) =
            make_float2(acc[nt][0] + b0 + x[r0 * 128 + col],
                        acc[nt][1] + b1 + x[r0 * 128 + col + 1]);
        *reinterpret_cast<float2*>(out + (r0 + 8) * 128 + col) =
            make_float2(acc[nt][2] + b0 + x[(r0 + 8) * 128 + col],
                        acc[nt][3] + b1 + x[(r0 + 8) * 128 + col + 1]);
    }
}

// ---------------- launch ----------------
extern "C" void kernel_launch(void* const* d_in, const int* in_sizes, int n_in,
                              void* d_out, int out_size) {
    (void)in_sizes; (void)n_in; (void)out_size;
    const float* x     = (const float*)d_in[0];
    const float* gamma = (const float*)d_in[1];
    const float* wq = (const float*)d_in[2];
    const float* bq = (const float*)d_in[3];
    const float* wk = (const float*)d_in[4];
    const float* bk = (const float*)d_in[5];
    const float* wv = (const float*)d_in[6];
    const float* bv = (const float*)d_in[7];
    const float* wo = (const float*)d_in[8];
    const float* bo = (const float*)d_in[9];
    float* out = (float*)d_out;

    cudaFuncSetAttribute(k_qkv,   cudaFuncAttributeMaxDynamicSharedMemorySize, 65536);
    cudaFuncSetAttribute(k_oproj, cudaFuncAttributeMaxDynamicSharedMemorySize, 65536);
    cudaFuncSetAttribute(k_attn,  cudaFuncAttributeMaxDynamicSharedMemorySize, 114688);

    k_norm <<<S / 8, 256>>>(x, gamma);
    k_wconv<<<dim3(64, 4), 256>>>(wq, wk, wv, wo);
    k_qkv  <<<dim3(S / 128, 3), 256, 65536>>>(bq, bk, bv);
    k_attn <<<NUNITS, 128, 114688>>>();
    k_comb <<<S / 64, 256>>>();
    k_oproj<<<S / 128, 256, 65536>>>(bo, x, out);
}